// round 15
// baseline (speedup 1.0000x reference)
#include <cuda_runtime.h>
#include <cuda_fp16.h>

// Problem constants (fixed by the reference)
#define NN 100000
#define EE 3200000
#define DD 16          // features per node
#define CAP 96         // bucket capacity; P(deg>=96) ~ 4e-20 under Poisson(32)

// coefficients: ALP = 0.5, LAM = 1.0 -> self coefficient is exactly 0
#define C_AGG 0.5f
#define C_X   0.5f

#define TB 256
#define GRID_E8 ((EE / 8 + TB - 1) / TB)
#define GRID_N  ((NN + TB - 1) / TB)
#define GRID_N2 ((NN * 2 + TB - 1) / TB)
#define GRID_N4 ((NN * 4 + TB - 1) / TB)

#define MASKBIT (1 << 30)
#define CNTMASK (MASKBIT - 1)

// ---------------- scratch (device globals; no allocation allowed) ----------
// g_cursor is (re)seeded every call by k_premask; g_nwork reset in k_premask.
// Every call performs identical work (graph-replay safe, deterministic).
__device__ int    g_cursor[NN];
__device__ float  g_dinv[NN];
__device__ int    g_deg[NN];
__device__ __align__(16) int g_col[NN * CAP];  // bucketed in-edge src lists (flat)
__device__ int    g_nwork;                     // number of unmasked nodes
__device__ int    g_worklist[NN];              // unmasked node ids (compacted)
// ping-pong state: ys = Y * dinv, fp16. Entry (node*2+q) = features 8q..8q+7
// as 8 halves in a uint4 (16B). Masked nodes are pre-seeded in BOTH buffers
// (their state never changes). Entries [NN*2..] are a zero sentinel.
__device__ uint4  g_ysh[2][NN * 2 + 2];

// ---------------- premask: fold mask into the fill counter -------------------
// cursor = MASKBIT for masked nodes -> k_fill's pos>=MASKBIT fails pos<CAP,
// so scatter stores to never-read masked buckets are skipped for free.
__global__ void k_premask(const int* __restrict__ mask) {
    int i = blockIdx.x * blockDim.x + threadIdx.x;
    if (i < NN) g_cursor[i] = (mask[i] != 0) ? MASKBIT : 0;
    if (i == 0) g_nwork = 0;
}

// ---------------- bucket fill (single atomic pass, 8 edges/thread) ----------
__global__ void k_fill(const int4* __restrict__ src4, const int4* __restrict__ dst4) {
    int e8 = blockIdx.x * blockDim.x + threadIdx.x;
    if (e8 < EE / 8) {
        #pragma unroll
        for (int u = 0; u < 2; u++) {
            int4 s = __ldcs(&src4[e8 * 2 + u]);   // streamed: read once per call
            int4 d = __ldcs(&dst4[e8 * 2 + u]);
            int pos;
            pos = atomicAdd(&g_cursor[d.x], 1); if (pos < CAP) g_col[d.x * CAP + pos] = s.x;
            pos = atomicAdd(&g_cursor[d.y], 1); if (pos < CAP) g_col[d.y * CAP + pos] = s.y;
            pos = atomicAdd(&g_cursor[d.z], 1); if (pos < CAP) g_col[d.z * CAP + pos] = s.z;
            pos = atomicAdd(&g_cursor[d.w], 1); if (pos < CAP) g_col[d.w * CAP + pos] = s.w;
        }
    }
}

__device__ __forceinline__ uint4 pack8h(const float* f) {
    __half2 h0 = __floats2half2_rn(f[0], f[1]);
    __half2 h1 = __floats2half2_rn(f[2], f[3]);
    __half2 h2 = __floats2half2_rn(f[4], f[5]);
    __half2 h3 = __floats2half2_rn(f[6], f[7]);
    uint4 r;
    r.x = *reinterpret_cast<unsigned int*>(&h0);
    r.y = *reinterpret_cast<unsigned int*>(&h1);
    r.z = *reinterpret_cast<unsigned int*>(&h2);
    r.w = *reinterpret_cast<unsigned int*>(&h3);
    return r;
}

// deg/dinv from cursor (count bits); pad unmasked col buckets; build worklist;
// seed ys (both buffers for masked; buf0 for unmasked); write masked yfinal=X.
// No cursor reset needed: k_premask rewrites it at the start of every call.
__global__ void k_init(const float4* __restrict__ X4,
                       const int* __restrict__ mask,
                       float4* __restrict__ yfinal) {
    int i = blockIdx.x * blockDim.x + threadIdx.x;   // over NN*2 uint4 entries
    if (i >= NN * 2) return;
    int node = i >> 1;
    int q = i & 1;
    int cur = g_cursor[node];
    int dg = cur & CNTMASK;
    if (dg > CAP) dg = CAP;
    bool m = (cur & MASKBIT) != 0;
    if (q == 0) {
        g_deg[node] = dg;
        g_dinv[node] = (dg > 0) ? rsqrtf((float)dg) : 0.0f;
        if (!m) {
            int dg8 = (dg + 7) & ~7;
            if (dg8 > CAP) dg8 = CAP;
            for (int p = dg; p < dg8; p++) g_col[node * CAP + p] = NN;  // sentinel
            int pos = atomicAdd(&g_nwork, 1);
            g_worklist[pos] = node;
        }
    }
    if (i == 0) {
        uint4 z = make_uint4(0, 0, 0, 0);
        g_ysh[0][NN * 2] = z; g_ysh[0][NN * 2 + 1] = z;
        g_ysh[1][NN * 2] = z; g_ysh[1][NN * 2 + 1] = z;
    }
    float di = (dg > 0) ? rsqrtf((float)dg) : 0.0f;
    float4 x0 = X4[node * 4 + 2 * q];
    float4 x1 = X4[node * 4 + 2 * q + 1];
    float f[8] = { x0.x * di, x0.y * di, x0.z * di, x0.w * di,
                   x1.x * di, x1.y * di, x1.z * di, x1.w * di };
    uint4 packed = pack8h(f);
    g_ysh[0][i] = packed;
    if (m) {
        g_ysh[1][i] = packed;                        // constant across all steps
        yfinal[node * 4 + 2 * q]     = x0;           // masked output = X
        yfinal[node * 4 + 2 * q + 1] = x1;
    }
}

// ---------------- propagation step (unmasked nodes only) --------------------
// 4 threads per worklist entry: h = edge-half (bit 1), q = feature-half (bit 0).
// Lane h walks alternating 8-edge chunks with two int4 col loads and 8
// independent LDG.128 gathers; halves combine via shfl_xor(2). R7 body.
__global__ __launch_bounds__(256) void k_prop(
    int bufin,
    const float4* __restrict__ X4,
    float4* __restrict__ yfinal,     // d_out on last step, else nullptr
    int write_ys)                    // 0 on last step
{
    int gid = blockIdx.x * blockDim.x + threadIdx.x;
    int unit = gid >> 2;
    if (unit >= g_nwork) return;
    int node = g_worklist[unit];
    int q = gid & 1;
    int h = (gid >> 1) & 1;

    const uint4* __restrict__ ys_in = g_ysh[bufin];
    int deg = g_deg[node];
    int deg8 = (deg + 7) & ~7;
    const int4* __restrict__ colv = (const int4*)(g_col + node * CAP);

    float acc[8] = {0.f, 0.f, 0.f, 0.f, 0.f, 0.f, 0.f, 0.f};

    // chunks of 8 edges; lane h takes chunks h, h+2, h+4, ...
    for (int j = h * 8; j < deg8; j += 16) {
        int4 c0 = __ldg(&colv[(j >> 2)]);
        int4 c1 = __ldg(&colv[(j >> 2) + 1]);
        int idx[8] = {c0.x, c0.y, c0.z, c0.w, c1.x, c1.y, c1.z, c1.w};
        uint4 v[8];
        #pragma unroll
        for (int t = 0; t < 8; t++)
            v[t] = __ldg(&ys_in[idx[t] * 2 + q]);
        #pragma unroll
        for (int t = 0; t < 8; t++) {
            float2 f0 = __half22float2(*reinterpret_cast<__half2*>(&v[t].x));
            float2 f1 = __half22float2(*reinterpret_cast<__half2*>(&v[t].y));
            float2 f2 = __half22float2(*reinterpret_cast<__half2*>(&v[t].z));
            float2 f3 = __half22float2(*reinterpret_cast<__half2*>(&v[t].w));
            acc[0] += f0.x; acc[1] += f0.y; acc[2] += f1.x; acc[3] += f1.y;
            acc[4] += f2.x; acc[5] += f2.y; acc[6] += f3.x; acc[7] += f3.y;
        }
    }

    // combine the two edge-halves (partner lane differs in bit 1)
    #pragma unroll
    for (int t = 0; t < 8; t++)
        acc[t] += __shfl_xor_sync(0xFFFFFFFFu, acc[t], 2, 32);

    if (h != 0) return;   // lane h=0 of each (node,q) does the epilogue

    float di = g_dinv[node];
    float4 x0 = X4[node * 4 + 2 * q];
    float4 x1 = X4[node * 4 + 2 * q + 1];
    float xf[8] = { x0.x, x0.y, x0.z, x0.w, x1.x, x1.y, x1.z, x1.w };

    float y[8];
    #pragma unroll
    for (int t = 0; t < 8; t++)
        y[t] = fminf(fmaxf(C_AGG * acc[t] * di + C_X * xf[t], -1.f), 1.f);

    if (write_ys) {
        float ys[8];
        #pragma unroll
        for (int t = 0; t < 8; t++) ys[t] = y[t] * di;
        g_ysh[bufin ^ 1][node * 2 + q] = pack8h(ys);
    }
    if (yfinal) {
        yfinal[node * 4 + 2 * q]     = make_float4(y[0], y[1], y[2], y[3]);
        yfinal[node * 4 + 2 * q + 1] = make_float4(y[4], y[5], y[6], y[7]);
    }
}

// ---------------- launch ----------------------------------------------------
extern "C" void kernel_launch(void* const* d_in, const int* in_sizes, int n_in,
                              void* d_out, int out_size) {
    // Defensive binding by element count (2E=6.4M, N*D=1.6M, N=100k distinct)
    const int* edge = nullptr;
    const float4* X4 = nullptr;
    const int* mask = nullptr;
    for (int i = 0; i < n_in; i++) {
        if (in_sizes[i] == 2 * EE)       edge = (const int*)d_in[i];
        else if (in_sizes[i] == NN * DD) X4   = (const float4*)d_in[i];
        else if (in_sizes[i] == NN)      mask = (const int*)d_in[i];
    }
    float4* out4 = (float4*)d_out;

    const int4* src4 = (const int4*)edge;
    const int4* dst4 = (const int4*)(edge + EE);

    k_premask<<<GRID_N, TB>>>(mask);               // launch 0
    k_fill<<<GRID_E8, TB>>>(src4, dst4);           // launch 1
    k_init<<<GRID_N2, TB>>>(X4, mask, out4);       // launch 2 (writes masked rows)

    int buf = 0;
    for (int step = 0; step < 5; step++) {         // launches 3..7
        int last = (step == 4);
        k_prop<<<GRID_N4, TB>>>(buf, X4,
                                last ? out4 : (float4*)nullptr,
                                last ? 0 : 1);
        buf ^= 1;
    }
}

// round 16
// speedup vs baseline: 1.3751x; 1.3751x over previous
#include <cuda_runtime.h>
#include <cuda_fp16.h>

// Problem constants (fixed by the reference)
#define NN 100000
#define EE 3200000
#define DD 16          // features per node
#define CAP 96         // bucket capacity; P(deg>=96) ~ 4e-20 under Poisson(32)

// coefficients: ALP = 0.5, LAM = 1.0 -> self coefficient is exactly 0
#define C_AGG 0.5f
#define C_X   0.5f

#define TB 256
#define TBP 128                              // k_prop block size (wave quantization)
#define GRID_E8 ((EE / 8 + TB - 1) / TB)
#define GRID_N2 ((NN * 2 + TB - 1) / TB)
#define GRID_P  ((NN * 4 + TBP - 1) / TBP)

// ---------------- scratch (device globals; no allocation allowed) ----------
// g_cursor/g_nwork start zero (module load) and are re-zeroed every call,
// so every call performs identical work (graph-replay safe, deterministic).
__device__ int    g_cursor[NN];
__device__ float  g_dinv[NN];
__device__ int    g_deg[NN];
__device__ __align__(16) int g_col[NN * CAP];  // bucketed in-edge src lists (flat)
__device__ int    g_nwork;                     // number of unmasked nodes
__device__ int    g_worklist[NN];              // unmasked node ids (compacted)
// ping-pong state: ys = Y * dinv, fp16. Entry (node*2+q) = features 8q..8q+7
// as 8 halves in a uint4 (16B). Masked nodes are pre-seeded in BOTH buffers
// (their state never changes). Entries [NN*2..] are a zero sentinel.
__device__ uint4  g_ysh[2][NN * 2 + 2];

// ---------------- bucket fill (single atomic pass, 8 edges/thread) ----------
__global__ void k_fill(const int4* __restrict__ src4, const int4* __restrict__ dst4) {
    if (blockIdx.x == 0 && threadIdx.x == 0) g_nwork = 0;  // reset for this call
    int e8 = blockIdx.x * blockDim.x + threadIdx.x;
    if (e8 < EE / 8) {
        #pragma unroll
        for (int u = 0; u < 2; u++) {
            int4 s = __ldcs(&src4[e8 * 2 + u]);   // streamed: read once per call
            int4 d = __ldcs(&dst4[e8 * 2 + u]);
            int pos;
            pos = atomicAdd(&g_cursor[d.x], 1); if (pos < CAP) g_col[d.x * CAP + pos] = s.x;
            pos = atomicAdd(&g_cursor[d.y], 1); if (pos < CAP) g_col[d.y * CAP + pos] = s.y;
            pos = atomicAdd(&g_cursor[d.z], 1); if (pos < CAP) g_col[d.z * CAP + pos] = s.z;
            pos = atomicAdd(&g_cursor[d.w], 1); if (pos < CAP) g_col[d.w * CAP + pos] = s.w;
        }
    }
}

__device__ __forceinline__ uint4 pack8h(const float* f) {
    __half2 h0 = __floats2half2_rn(f[0], f[1]);
    __half2 h1 = __floats2half2_rn(f[2], f[3]);
    __half2 h2 = __floats2half2_rn(f[4], f[5]);
    __half2 h3 = __floats2half2_rn(f[6], f[7]);
    uint4 r;
    r.x = *reinterpret_cast<unsigned int*>(&h0);
    r.y = *reinterpret_cast<unsigned int*>(&h1);
    r.z = *reinterpret_cast<unsigned int*>(&h2);
    r.w = *reinterpret_cast<unsigned int*>(&h3);
    return r;
}

// deg/dinv from cursor; reset cursor; pad col bucket; build unmasked worklist;
// seed ys (both buffers for masked; buf0 for unmasked); write masked yfinal=X.
__global__ void k_init(const float4* __restrict__ X4,
                       const int* __restrict__ mask,
                       float4* __restrict__ yfinal) {
    int i = blockIdx.x * blockDim.x + threadIdx.x;   // over NN*2 uint4 entries
    if (i >= NN * 2) return;
    int node = i >> 1;
    int q = i & 1;
    int dg = g_cursor[node];                         // both lanes load (pre-store)
    if (dg > CAP) dg = CAP;
    bool m = (mask[node] != 0);
    if (q == 0) {
        g_deg[node] = dg;
        g_dinv[node] = (dg > 0) ? rsqrtf((float)dg) : 0.0f;
        g_cursor[node] = 0;                          // reset for next call
        int dg8 = (dg + 7) & ~7;
        if (dg8 > CAP) dg8 = CAP;
        for (int p = dg; p < dg8; p++) g_col[node * CAP + p] = NN;  // sentinel
        if (!m) {
            int pos = atomicAdd(&g_nwork, 1);
            g_worklist[pos] = node;
        }
    }
    if (i == 0) {
        uint4 z = make_uint4(0, 0, 0, 0);
        g_ysh[0][NN * 2] = z; g_ysh[0][NN * 2 + 1] = z;
        g_ysh[1][NN * 2] = z; g_ysh[1][NN * 2 + 1] = z;
    }
    float di = (dg > 0) ? rsqrtf((float)dg) : 0.0f;
    float4 x0 = X4[node * 4 + 2 * q];
    float4 x1 = X4[node * 4 + 2 * q + 1];
    float f[8] = { x0.x * di, x0.y * di, x0.z * di, x0.w * di,
                   x1.x * di, x1.y * di, x1.z * di, x1.w * di };
    uint4 packed = pack8h(f);
    g_ysh[0][i] = packed;
    if (m) {
        g_ysh[1][i] = packed;                        // constant across all steps
        yfinal[node * 4 + 2 * q]     = x0;           // masked output = X
        yfinal[node * 4 + 2 * q + 1] = x1;
    }
}

// ---------------- propagation step (unmasked nodes only) --------------------
// 4 threads per worklist entry: h = edge-half (bit 1), q = feature-half (bit 0).
// Lane h walks alternating 8-edge chunks with two int4 col loads and 8
// independent LDG.128 gathers; halves combine via shfl_xor(2). R7/R14 body,
// TB=128 blocks for finer wave quantization.
__global__ __launch_bounds__(TBP) void k_prop(
    int bufin,
    const float4* __restrict__ X4,
    float4* __restrict__ yfinal,     // d_out on last step, else nullptr
    int write_ys)                    // 0 on last step
{
    int gid = blockIdx.x * blockDim.x + threadIdx.x;
    int unit = gid >> 2;
    if (unit >= g_nwork) return;
    int node = g_worklist[unit];
    int q = gid & 1;
    int h = (gid >> 1) & 1;

    const uint4* __restrict__ ys_in = g_ysh[bufin];
    int deg = g_deg[node];
    int deg8 = (deg + 7) & ~7;
    const int4* __restrict__ colv = (const int4*)(g_col + node * CAP);

    float acc[8] = {0.f, 0.f, 0.f, 0.f, 0.f, 0.f, 0.f, 0.f};

    // chunks of 8 edges; lane h takes chunks h, h+2, h+4, ...
    for (int j = h * 8; j < deg8; j += 16) {
        int4 c0 = __ldg(&colv[(j >> 2)]);
        int4 c1 = __ldg(&colv[(j >> 2) + 1]);
        int idx[8] = {c0.x, c0.y, c0.z, c0.w, c1.x, c1.y, c1.z, c1.w};
        uint4 v[8];
        #pragma unroll
        for (int t = 0; t < 8; t++)
            v[t] = __ldg(&ys_in[idx[t] * 2 + q]);
        #pragma unroll
        for (int t = 0; t < 8; t++) {
            float2 f0 = __half22float2(*reinterpret_cast<__half2*>(&v[t].x));
            float2 f1 = __half22float2(*reinterpret_cast<__half2*>(&v[t].y));
            float2 f2 = __half22float2(*reinterpret_cast<__half2*>(&v[t].z));
            float2 f3 = __half22float2(*reinterpret_cast<__half2*>(&v[t].w));
            acc[0] += f0.x; acc[1] += f0.y; acc[2] += f1.x; acc[3] += f1.y;
            acc[4] += f2.x; acc[5] += f2.y; acc[6] += f3.x; acc[7] += f3.y;
        }
    }

    // combine the two edge-halves (partner lane differs in bit 1)
    #pragma unroll
    for (int t = 0; t < 8; t++)
        acc[t] += __shfl_xor_sync(0xFFFFFFFFu, acc[t], 2, 32);

    if (h != 0) return;   // lane h=0 of each (node,q) does the epilogue

    float di = g_dinv[node];
    float4 x0 = X4[node * 4 + 2 * q];
    float4 x1 = X4[node * 4 + 2 * q + 1];
    float xf[8] = { x0.x, x0.y, x0.z, x0.w, x1.x, x1.y, x1.z, x1.w };

    float y[8];
    #pragma unroll
    for (int t = 0; t < 8; t++)
        y[t] = fminf(fmaxf(C_AGG * acc[t] * di + C_X * xf[t], -1.f), 1.f);

    if (write_ys) {
        float ys[8];
        #pragma unroll
        for (int t = 0; t < 8; t++) ys[t] = y[t] * di;
        g_ysh[bufin ^ 1][node * 2 + q] = pack8h(ys);
    }
    if (yfinal) {
        yfinal[node * 4 + 2 * q]     = make_float4(y[0], y[1], y[2], y[3]);
        yfinal[node * 4 + 2 * q + 1] = make_float4(y[4], y[5], y[6], y[7]);
    }
}

// ---------------- launch ----------------------------------------------------
extern "C" void kernel_launch(void* const* d_in, const int* in_sizes, int n_in,
                              void* d_out, int out_size) {
    // Defensive binding by element count (2E=6.4M, N*D=1.6M, N=100k distinct)
    const int* edge = nullptr;
    const float4* X4 = nullptr;
    const int* mask = nullptr;
    for (int i = 0; i < n_in; i++) {
        if (in_sizes[i] == 2 * EE)       edge = (const int*)d_in[i];
        else if (in_sizes[i] == NN * DD) X4   = (const float4*)d_in[i];
        else if (in_sizes[i] == NN)      mask = (const int*)d_in[i];
    }
    float4* out4 = (float4*)d_out;

    const int4* src4 = (const int4*)edge;
    const int4* dst4 = (const int4*)(edge + EE);

    k_fill<<<GRID_E8, TB>>>(src4, dst4);           // launch 0
    k_init<<<GRID_N2, TB>>>(X4, mask, out4);       // launch 1 (writes masked rows)

    int buf = 0;
    for (int step = 0; step < 5; step++) {         // launches 2..6
        int last = (step == 4);
        k_prop<<<GRID_P, TBP>>>(buf, X4,
                                last ? out4 : (float4*)nullptr,
                                last ? 0 : 1);
        buf ^= 1;
    }
}

// round 17
// speedup vs baseline: 1.4396x; 1.0469x over previous
#include <cuda_runtime.h>
#include <cuda_fp16.h>

// Problem constants (fixed by the reference)
#define NN 100000
#define EE 3200000
#define DD 16          // features per node
#define CAP 96         // bucket capacity; P(deg>=96) ~ 4e-20 under Poisson(32)

// coefficients: ALP = 0.5, LAM = 1.0 -> self coefficient is exactly 0
#define C_AGG 0.5f
#define C_X   0.5f

#define TB 256
#define TBP 128                              // k_prop block size (wave quantization)
#define GRID_E8 ((EE / 8 + TB - 1) / TB)
#define GRID_N  ((NN + TB - 1) / TB)
#define GRID_N2 ((NN * 2 + TB - 1) / TB)
#define GRID_P  ((NN * 4 + TBP - 1) / TBP)

#define MASKBIT (1 << 30)
#define CNTMASK (MASKBIT - 1)

// ---------------- scratch (device globals; no allocation allowed) ----------
// g_cursor is (re)seeded at the start of every call by k_premask (which also
// resets g_nwork), so every call performs identical work (graph-replay safe).
__device__ int    g_cursor[NN];
__device__ float  g_dinv[NN];
__device__ int    g_deg[NN];
__device__ __align__(16) int g_col[NN * CAP];  // bucketed in-edge src lists (flat)
__device__ int    g_nwork;                     // number of unmasked nodes
__device__ int    g_worklist[NN];              // unmasked node ids (compacted)
// ping-pong state: ys = Y * dinv, fp16. Entry (node*2+q) = features 8q..8q+7
// as 8 halves in a uint4 (16B). Masked nodes are pre-seeded in BOTH buffers
// (their state never changes). Entries [NN*2..] are a zero sentinel.
__device__ uint4  g_ysh[2][NN * 2 + 2];

// ---------------- premask: fold mask into the fill counter -------------------
// cursor = MASKBIT for masked nodes -> k_fill's pos >= MASKBIT fails pos<CAP,
// so scatter stores to never-read masked buckets are skipped for free.
__global__ void k_premask(const int* __restrict__ mask) {
    int i = blockIdx.x * blockDim.x + threadIdx.x;
    if (i < NN) g_cursor[i] = (mask[i] != 0) ? MASKBIT : 0;
    if (i == 0) g_nwork = 0;
}

// ---------------- bucket fill (single atomic pass, 8 edges/thread) ----------
__global__ void k_fill(const int4* __restrict__ src4, const int4* __restrict__ dst4) {
    int e8 = blockIdx.x * blockDim.x + threadIdx.x;
    if (e8 < EE / 8) {
        #pragma unroll
        for (int u = 0; u < 2; u++) {
            int4 s = __ldcs(&src4[e8 * 2 + u]);   // streamed: read once per call
            int4 d = __ldcs(&dst4[e8 * 2 + u]);
            int pos;
            pos = atomicAdd(&g_cursor[d.x], 1); if (pos < CAP) g_col[d.x * CAP + pos] = s.x;
            pos = atomicAdd(&g_cursor[d.y], 1); if (pos < CAP) g_col[d.y * CAP + pos] = s.y;
            pos = atomicAdd(&g_cursor[d.z], 1); if (pos < CAP) g_col[d.z * CAP + pos] = s.z;
            pos = atomicAdd(&g_cursor[d.w], 1); if (pos < CAP) g_col[d.w * CAP + pos] = s.w;
        }
    }
}

__device__ __forceinline__ uint4 pack8h(const float* f) {
    __half2 h0 = __floats2half2_rn(f[0], f[1]);
    __half2 h1 = __floats2half2_rn(f[2], f[3]);
    __half2 h2 = __floats2half2_rn(f[4], f[5]);
    __half2 h3 = __floats2half2_rn(f[6], f[7]);
    uint4 r;
    r.x = *reinterpret_cast<unsigned int*>(&h0);
    r.y = *reinterpret_cast<unsigned int*>(&h1);
    r.z = *reinterpret_cast<unsigned int*>(&h2);
    r.w = *reinterpret_cast<unsigned int*>(&h3);
    return r;
}

// deg/dinv from cursor (count bits, mask bit); pad unmasked col buckets;
// build worklist; seed ys (both buffers for masked); write masked yfinal=X.
// No cursor reset needed: k_premask rewrites it at the start of every call.
__global__ void k_init(const float4* __restrict__ X4,
                       float4* __restrict__ yfinal) {
    int i = blockIdx.x * blockDim.x + threadIdx.x;   // over NN*2 uint4 entries
    if (i >= NN * 2) return;
    int node = i >> 1;
    int q = i & 1;
    int cur = g_cursor[node];
    int dg = cur & CNTMASK;
    if (dg > CAP) dg = CAP;
    bool m = (cur & MASKBIT) != 0;
    if (q == 0) {
        g_deg[node] = dg;
        g_dinv[node] = (dg > 0) ? rsqrtf((float)dg) : 0.0f;
        if (!m) {
            int dg8 = (dg + 7) & ~7;
            if (dg8 > CAP) dg8 = CAP;
            for (int p = dg; p < dg8; p++) g_col[node * CAP + p] = NN;  // sentinel
            int pos = atomicAdd(&g_nwork, 1);
            g_worklist[pos] = node;
        }
    }
    if (i == 0) {
        uint4 z = make_uint4(0, 0, 0, 0);
        g_ysh[0][NN * 2] = z; g_ysh[0][NN * 2 + 1] = z;
        g_ysh[1][NN * 2] = z; g_ysh[1][NN * 2 + 1] = z;
    }
    float di = (dg > 0) ? rsqrtf((float)dg) : 0.0f;
    float4 x0 = X4[node * 4 + 2 * q];
    float4 x1 = X4[node * 4 + 2 * q + 1];
    float f[8] = { x0.x * di, x0.y * di, x0.z * di, x0.w * di,
                   x1.x * di, x1.y * di, x1.z * di, x1.w * di };
    uint4 packed = pack8h(f);
    g_ysh[0][i] = packed;
    if (m) {
        g_ysh[1][i] = packed;                        // constant across all steps
        yfinal[node * 4 + 2 * q]     = x0;           // masked output = X
        yfinal[node * 4 + 2 * q + 1] = x1;
    }
}

// ---------------- propagation step (unmasked nodes only) --------------------
// 4 threads per worklist entry: h = edge-half (bit 1), q = feature-half (bit 0).
// Lane h walks alternating 8-edge chunks with two int4 col loads and 8
// independent LDG.128 gathers; halves combine via shfl_xor(2). R16 body,
// TB=128 blocks for finer wave quantization.
__global__ __launch_bounds__(TBP) void k_prop(
    int bufin,
    const float4* __restrict__ X4,
    float4* __restrict__ yfinal,     // d_out on last step, else nullptr
    int write_ys)                    // 0 on last step
{
    int gid = blockIdx.x * blockDim.x + threadIdx.x;
    int unit = gid >> 2;
    if (unit >= g_nwork) return;
    int node = g_worklist[unit];
    int q = gid & 1;
    int h = (gid >> 1) & 1;

    const uint4* __restrict__ ys_in = g_ysh[bufin];
    int deg = g_deg[node];
    int deg8 = (deg + 7) & ~7;
    const int4* __restrict__ colv = (const int4*)(g_col + node * CAP);

    float acc[8] = {0.f, 0.f, 0.f, 0.f, 0.f, 0.f, 0.f, 0.f};

    // chunks of 8 edges; lane h takes chunks h, h+2, h+4, ...
    for (int j = h * 8; j < deg8; j += 16) {
        int4 c0 = __ldg(&colv[(j >> 2)]);
        int4 c1 = __ldg(&colv[(j >> 2) + 1]);
        int idx[8] = {c0.x, c0.y, c0.z, c0.w, c1.x, c1.y, c1.z, c1.w};
        uint4 v[8];
        #pragma unroll
        for (int t = 0; t < 8; t++)
            v[t] = __ldg(&ys_in[idx[t] * 2 + q]);
        #pragma unroll
        for (int t = 0; t < 8; t++) {
            float2 f0 = __half22float2(*reinterpret_cast<__half2*>(&v[t].x));
            float2 f1 = __half22float2(*reinterpret_cast<__half2*>(&v[t].y));
            float2 f2 = __half22float2(*reinterpret_cast<__half2*>(&v[t].z));
            float2 f3 = __half22float2(*reinterpret_cast<__half2*>(&v[t].w));
            acc[0] += f0.x; acc[1] += f0.y; acc[2] += f1.x; acc[3] += f1.y;
            acc[4] += f2.x; acc[5] += f2.y; acc[6] += f3.x; acc[7] += f3.y;
        }
    }

    // combine the two edge-halves (partner lane differs in bit 1)
    #pragma unroll
    for (int t = 0; t < 8; t++)
        acc[t] += __shfl_xor_sync(0xFFFFFFFFu, acc[t], 2, 32);

    if (h != 0) return;   // lane h=0 of each (node,q) does the epilogue

    float di = g_dinv[node];
    float4 x0 = X4[node * 4 + 2 * q];
    float4 x1 = X4[node * 4 + 2 * q + 1];
    float xf[8] = { x0.x, x0.y, x0.z, x0.w, x1.x, x1.y, x1.z, x1.w };

    float y[8];
    #pragma unroll
    for (int t = 0; t < 8; t++)
        y[t] = fminf(fmaxf(C_AGG * acc[t] * di + C_X * xf[t], -1.f), 1.f);

    if (write_ys) {
        float ys[8];
        #pragma unroll
        for (int t = 0; t < 8; t++) ys[t] = y[t] * di;
        g_ysh[bufin ^ 1][node * 2 + q] = pack8h(ys);
    }
    if (yfinal) {
        yfinal[node * 4 + 2 * q]     = make_float4(y[0], y[1], y[2], y[3]);
        yfinal[node * 4 + 2 * q + 1] = make_float4(y[4], y[5], y[6], y[7]);
    }
}

// ---------------- launch ----------------------------------------------------
extern "C" void kernel_launch(void* const* d_in, const int* in_sizes, int n_in,
                              void* d_out, int out_size) {
    // Defensive binding by element count (2E=6.4M, N*D=1.6M, N=100k distinct)
    const int* edge = nullptr;
    const float4* X4 = nullptr;
    const int* mask = nullptr;
    for (int i = 0; i < n_in; i++) {
        if (in_sizes[i] == 2 * EE)       edge = (const int*)d_in[i];
        else if (in_sizes[i] == NN * DD) X4   = (const float4*)d_in[i];
        else if (in_sizes[i] == NN)      mask = (const int*)d_in[i];
    }
    float4* out4 = (float4*)d_out;

    const int4* src4 = (const int4*)edge;
    const int4* dst4 = (const int4*)(edge + EE);

    k_premask<<<GRID_N, TB>>>(mask);               // launch 0
    k_fill<<<GRID_E8, TB>>>(src4, dst4);           // launch 1
    k_init<<<GRID_N2, TB>>>(X4, out4);             // launch 2 (writes masked rows)

    int buf = 0;
    for (int step = 0; step < 5; step++) {         // launches 3..7
        int last = (step == 4);
        k_prop<<<GRID_P, TBP>>>(buf, X4,
                                last ? out4 : (float4*)nullptr,
                                last ? 0 : 1);
        buf ^= 1;
    }
}